// round 15
// baseline (speedup 1.0000x reference)
#include <cuda_runtime.h>
#include <stdint.h>
#include <limits.h>

// Problem constants (match reference)
#define HOP        160
#define FFT        1024
#define NUM_LABELS 72
#define BATCH      4
#define TLEN       240000
#define PAD        (FFT / 2)           // 512
#define LPAD       (TLEN + 2 * PAD)    // 241024
#define NOUT       ((LPAD - FFT) / HOP + 1)  // 1501

// Window w = padded [160w, 160w+1024) = segments [5w, 5w+32), 32-el segments.
#define SEGLEN        32
#define SEGS_PER_WIN  32
#define WINS_PER_CTA  32
#define SEGS_PER_CTA  187                 // 5*32 + 27
#define TOTAL_SEGS    (LPAD / SEGLEN)     // 7532
#define NWORDS        36                  // 72 bins as u16 pairs (2 bins / u32)
#define WARPS         8
#define BLOCK         (WARPS * 32)
#define CTAS_X        47                  // ceil(1501/32)
#define W_PER_WARP    4

__device__ __forceinline__ int reflect_idx(int j)   // j = padded index
{
    int o = j - PAD;
    if (o < 0) o = -o;
    else if (o >= TLEN) o = 2 * (TLEN - 1) - o;
    return o;
}

// Argmax: lane c<18 owns bins 4c..4c+3 held in two u16x2 accumulators.
// Lowest-label tie-break (matches jnp.argmax): pack count<<7 | (127-label).
__device__ __forceinline__ void scan_write(uint32_t a0, uint32_t a1,
                                           int lane, float* __restrict__ orow,
                                           int w)
{
    int p = INT_MIN;
    if (lane < 18) {
        int b0 = 4 * lane;
        p =         ((int)(a0 & 0xFFFFu) << 7) | (127 - b0);        // bin 4c
        p = max(p, ((int)(a0 >> 16)     << 7) | (127 - (b0 + 1)));  // bin 4c+1
        p = max(p, ((int)(a1 & 0xFFFFu) << 7) | (127 - (b0 + 2)));  // bin 4c+2
        p = max(p, ((int)(a1 >> 16)     << 7) | (127 - (b0 + 3)));  // bin 4c+3
    }
    p = __reduce_max_sync(0xFFFFFFFFu, p);
    if (lane == 0 && w < NOUT)
        orow[w] = (float)(127 - (p & 127));
}

__global__ void __launch_bounds__(BLOCK)
label_majority_matchhist(const int* __restrict__ lbl, float* __restrict__ out)
{
    // Column-major: sh[word * 187 + seg], word = bin>>1 (u16 pair per u32).
    __shared__ uint32_t sh[NWORDS * SEGS_PER_CTA];

    const int tid  = threadIdx.x;
    const int lane = tid & 31;
    const int wid  = tid >> 5;
    const int b    = blockIdx.y;
    const int bx   = blockIdx.x;
    const int w0   = bx * WINS_PER_CTA;
    const int gseg0 = 5 * w0;

    const int* __restrict__ row  = lbl + (size_t)b * TLEN;
    float* __restrict__     orow = out + (size_t)b * NOUT;

    for (int i = tid; i < NWORDS * SEGS_PER_CTA; i += BLOCK)
        sh[i] = 0;
    __syncthreads();

    // ============ phase 1: one MATCH per segment ===========================
    // Segment <-> 32 lanes (coalesced 4B loads). match_any groups equal
    // labels; each group leader stores popc as u16. Distinct labels ->
    // distinct u16 addresses: plain stores, no atomics, no RMW.
    {
        unsigned short* __restrict__ sh16 = (unsigned short*)sh;
        #pragma unroll
        for (int s = wid; s < SEGS_PER_CTA; s += WARPS) {   // 23-24 iters/warp
            const int gseg = gseg0 + s;
            if (gseg < TOTAL_SEGS) {
                int v = row[reflect_idx(gseg * SEGLEN + lane)];
                unsigned m = __match_any_sync(0xFFFFFFFFu, v);
                if (lane == (__ffs(m) - 1)) {
                    // u16 slot: word (v>>1) column s, half (v&1)
                    sh16[((v >> 1) * SEGS_PER_CTA + s) * 2 + (v & 1)] =
                        (unsigned short)__popc(m);
                }
            }
        }
    }
    __syncthreads();

    // ============ phase 2: sliding window sums (no atomics) ================
    // Warp handles windows w0 + 4*wid + i. Lane c<18 sums words 2c, 2c+1
    // over the window's 32 segments; u16 fields never borrow/carry:
    // per-seg values <=32, window sums <=1024, and slides add before subtract.
    const int wrel0 = wid * W_PER_WARP;
    const int srel0 = 5 * wrel0;
    const uint32_t* __restrict__ c0 = sh + (2 * lane)     * SEGS_PER_CTA + srel0;
    const uint32_t* __restrict__ c1 = sh + (2 * lane + 1) * SEGS_PER_CTA + srel0;

    uint32_t a0 = 0, a1 = 0;
    if (lane < 18) {
        #pragma unroll
        for (int k = 0; k < SEGS_PER_WIN; k++) {
            a0 += c0[k];
            a1 += c1[k];
        }
    }
    scan_write(a0, a1, lane, orow, w0 + wrel0);

    #pragma unroll
    for (int i = 1; i < W_PER_WARP; i++) {
        if (lane < 18) {
            const int so = 5 * (i - 1);
            #pragma unroll
            for (int k = 0; k < 5; k++) {
                a0 = a0 + c0[so + SEGS_PER_WIN + k] - c0[so + k];
                a1 = a1 + c1[so + SEGS_PER_WIN + k] - c1[so + k];
            }
        }
        scan_write(a0, a1, lane, orow, w0 + wrel0 + i);
    }
}

extern "C" void kernel_launch(void* const* d_in, const int* in_sizes, int n_in,
                              void* d_out, int out_size)
{
    const int* lbl = (const int*)d_in[0];   // [B, T] int32
    // d_in[1]: all-ones conv weight — irrelevant (window sum == histogram).
    float* out = (float*)d_out;             // [B, NOUT], compared as float32

    dim3 grid(CTAS_X, BATCH);
    label_majority_matchhist<<<grid, BLOCK>>>(lbl, out);
}

// round 16
// speedup vs baseline: 1.9211x; 1.9211x over previous
#include <cuda_runtime.h>
#include <stdint.h>
#include <limits.h>

// Problem constants (match reference)
#define HOP        160
#define FFT        1024
#define NUM_LABELS 72
#define BATCH      4
#define TLEN       240000
#define PAD        (FFT / 2)           // 512
#define LPAD       (TLEN + 2 * PAD)    // 241024
#define NOUT       ((LPAD - FFT) / HOP + 1)  // 1501

// 16-element segments: window w = padded [160w,160w+1024) = segs [10w,10w+64)
#define SEGLEN        16
#define SEGS_PER_WIN  64
#define WINS_PER_CTA  16
#define SEGS_PER_CTA  214                // 10*16 + 54
#define TOTAL_SEGS    (LPAD / SEGLEN)    // 15064
#define NWORDS        36                 // 72 bins as u16 pairs
#define PITCH         215                // padded (odd) word pitch
#define WARPS         8
#define BLOCK         (WARPS * 32)
#define CTAS_X        94                 // ceil(1501/16) -> 376 CTAs total
#define CHUNKS        27                 // ceil(214*16/128); chunk = 128 elem

__device__ __forceinline__ int reflect_idx(int j)   // j = padded index
{
    int o = j - PAD;
    if (o < 0) o = -o;
    else if (o >= TLEN) o = 2 * (TLEN - 1) - o;
    return o;
}

// Argmax: lane c<18 owns bins 4c..4c+3 in two u16x2 accumulators.
// Lowest-label tie-break (matches jnp.argmax).
__device__ __forceinline__ void scan_write(uint32_t a0, uint32_t a1,
                                           int lane, float* __restrict__ orow,
                                           int w)
{
    int p = INT_MIN;
    if (lane < 18) {
        int b0 = 4 * lane;
        p =         ((int)(a0 & 0xFFFFu) << 7) | (127 - b0);        // bin 4c
        p = max(p, ((int)(a0 >> 16)     << 7) | (127 - (b0 + 1)));  // bin 4c+1
        p = max(p, ((int)(a1 & 0xFFFFu) << 7) | (127 - (b0 + 2)));  // bin 4c+2
        p = max(p, ((int)(a1 >> 16)     << 7) | (127 - (b0 + 3)));  // bin 4c+3
    }
    p = __reduce_max_sync(0xFFFFFFFFu, p);
    if (lane == 0 && w < NOUT)
        orow[w] = (float)(127 - (p & 127));
}

__global__ void __launch_bounds__(BLOCK)
label_majority_seg16(const int* __restrict__ lbl, float* __restrict__ out)
{
    // Word-major: sh[word * PITCH + seg]. 36*215*4 = 30960 B.
    __shared__ uint32_t sh[NWORDS * PITCH];

    const int tid  = threadIdx.x;
    const int lane = tid & 31;
    const int wid  = tid >> 5;
    const int b    = blockIdx.y;
    const int bx   = blockIdx.x;
    const int w0   = bx * WINS_PER_CTA;
    const int gseg0 = 10 * w0;            // = 160*bx, 16-el segment units

    const int* __restrict__ row  = lbl + (size_t)b * TLEN;
    float* __restrict__     orow = out + (size_t)b * NOUT;

    for (int i = tid; i < NWORDS * PITCH; i += BLOCK)
        sh[i] = 0;
    __syncthreads();

    // ============ phase 1: one-touch packed segment histograms =============
    // Chunk = 128 consecutive elements = 8 segments; int4 per lane (coalesced).
    // Each atomic instruction: 8 segments x 4 lanes -> same-word collisions
    // only among 4 lanes over 36 words (replay ~1.17). u16 halves, counts<=16.
    {
        int4 q[4];
        bool valid[4];
        if (bx >= 1 && bx <= 92) {
            // interior: unpadded base, 16B-aligned ((2560*bx-512)*4 % 16 == 0)
            const int* __restrict__ basep = row + (gseg0 * SEGLEN - PAD);
            #pragma unroll
            for (int t = 0; t < 4; t++) {
                int c = wid + 8 * t;
                valid[t] = (c < CHUNKS);
                if (valid[t]) q[t] = *(const int4*)(basep + c * 128 + lane * 4);
            }
        } else {
            // edge CTAs (bx==0, bx==93): reflect-mapped scalar prefetch
            #pragma unroll
            for (int t = 0; t < 4; t++) {
                int c = wid + 8 * t;
                valid[t] = false;
                if (c < CHUNKS) {
                    int e   = c * 128 + lane * 4;
                    int seg = e >> 4;
                    if (seg < SEGS_PER_CTA && (gseg0 + seg) < TOTAL_SEGS) {
                        int j0 = gseg0 * SEGLEN + e;
                        q[t].x = row[reflect_idx(j0)];
                        q[t].y = row[reflect_idx(j0 + 1)];
                        q[t].z = row[reflect_idx(j0 + 2)];
                        q[t].w = row[reflect_idx(j0 + 3)];
                        valid[t] = true;
                    }
                }
            }
        }
        #pragma unroll
        for (int t = 0; t < 4; t++) {
            if (valid[t]) {
                int c   = wid + 8 * t;
                int seg = 8 * c + (lane >> 2);
                if (seg < SEGS_PER_CTA) {   // interior chunk-26 tail guard
                    atomicAdd(&sh[(uint32_t)(q[t].x >> 1) * PITCH + seg],
                              1u << ((q[t].x & 1) * 16));
                    atomicAdd(&sh[(uint32_t)(q[t].y >> 1) * PITCH + seg],
                              1u << ((q[t].y & 1) * 16));
                    atomicAdd(&sh[(uint32_t)(q[t].z >> 1) * PITCH + seg],
                              1u << ((q[t].z & 1) * 16));
                    atomicAdd(&sh[(uint32_t)(q[t].w >> 1) * PITCH + seg],
                              1u << ((q[t].w & 1) * 16));
                }
            }
        }
    }
    __syncthreads();

    // ============ phase 2: window sums + one slide (no atomics) ============
    // Warp handles windows w0 + 2*wid {+1}. Lane c<18 sums words 2c, 2c+1
    // over 64 segments; u16 fields: window sums <=1024, add-before-subtract.
    const int wrel0 = 2 * wid;
    const int srel  = 10 * wrel0;
    const uint32_t* __restrict__ c0 = sh + (2 * lane)     * PITCH + srel;
    const uint32_t* __restrict__ c1 = sh + (2 * lane + 1) * PITCH + srel;

    uint32_t a0 = 0, a1 = 0;
    if (lane < 18) {
        #pragma unroll
        for (int k = 0; k < SEGS_PER_WIN; k++) {
            a0 += c0[k];
            a1 += c1[k];
        }
    }
    scan_write(a0, a1, lane, orow, w0 + wrel0);

    if (lane < 18) {
        #pragma unroll
        for (int k = 0; k < 10; k++) {
            a0 = a0 + c0[SEGS_PER_WIN + k] - c0[k];
            a1 = a1 + c1[SEGS_PER_WIN + k] - c1[k];
        }
    }
    scan_write(a0, a1, lane, orow, w0 + wrel0 + 1);
}

extern "C" void kernel_launch(void* const* d_in, const int* in_sizes, int n_in,
                              void* d_out, int out_size)
{
    const int* lbl = (const int*)d_in[0];   // [B, T] int32
    // d_in[1]: all-ones conv weight — irrelevant (window sum == histogram).
    float* out = (float*)d_out;             // [B, NOUT], compared as float32

    dim3 grid(CTAS_X, BATCH);
    label_majority_seg16<<<grid, BLOCK>>>(lbl, out);
}

// round 17
// speedup vs baseline: 1.9281x; 1.0036x over previous
#include <cuda_runtime.h>
#include <stdint.h>
#include <limits.h>

// Problem constants (match reference)
#define HOP        160
#define FFT        1024
#define NUM_LABELS 72
#define BATCH      4
#define TLEN       240000
#define PAD        (FFT / 2)           // 512
#define LPAD       (TLEN + 2 * PAD)    // 241024
#define NOUT       ((LPAD - FFT) / HOP + 1)  // 1501

// 16-element segments: window w = padded [160w,160w+1024) = segs [10w,10w+64)
#define SEGLEN        16
#define SEGS_PER_WIN  64
#define WINS_PER_CTA  8
#define SEGS_PER_CTA  134                // 10*8 + 54
#define TOTAL_SEGS    (LPAD / SEGLEN)    // 15064
#define NWORDS        18                 // 72 bins byte-packed 4-per-u32
#define PITCH         135                // odd pitch -> conflict-free columns
#define WARPS         4
#define BLOCK         (WARPS * 32)       // 128
#define CTAS_X        188                // ceil(1501/8) -> 752 CTAs total
#define CHUNKS        17                 // ceil(134*16/128); chunk = 128 elem

__device__ __forceinline__ int reflect_idx(int j)   // j = padded index
{
    int o = j - PAD;
    if (o < 0) o = -o;
    else if (o >= TLEN) o = 2 * (TLEN - 1) - o;
    return o;
}

// Argmax: lane c<18 owns bins 4c..4c+3; accE=(4c,4c+2) accO=(4c+1,4c+3) u16x2.
// Lowest-label tie-break (matches jnp.argmax).
__device__ __forceinline__ void scan_write(uint32_t accE, uint32_t accO,
                                           int lane, float* __restrict__ orow,
                                           int w)
{
    int p = INT_MIN;
    if (lane < NWORDS) {
        int b0 = 4 * lane;
        p =         ((int)(accE & 0xFFFFu) << 7) | (127 - b0);
        p = max(p, ((int)(accO & 0xFFFFu) << 7) | (127 - (b0 + 1)));
        p = max(p, ((int)(accE >> 16)     << 7) | (127 - (b0 + 2)));
        p = max(p, ((int)(accO >> 16)     << 7) | (127 - (b0 + 3)));
    }
    p = __reduce_max_sync(0xFFFFFFFFu, p);
    if (lane == 0 && w < NOUT)
        orow[w] = (float)(127 - (p & 127));
}

__global__ void __launch_bounds__(BLOCK)
label_majority_seg16s(const int* __restrict__ lbl, float* __restrict__ out)
{
    // Word-major: sh[word * PITCH + seg]; 18*135*4 = 9720 B -> high occupancy.
    __shared__ uint32_t sh[NWORDS * PITCH];

    const int tid  = threadIdx.x;
    const int lane = tid & 31;
    const int wid  = tid >> 5;
    const int b    = blockIdx.y;
    const int bx   = blockIdx.x;
    const int w0   = bx * WINS_PER_CTA;
    const int gseg0 = 10 * w0;            // 16-el segment units (=80*bx)

    const int* __restrict__ row  = lbl + (size_t)b * TLEN;
    float* __restrict__     orow = out + (size_t)b * NOUT;

    for (int i = tid; i < NWORDS * PITCH; i += BLOCK)
        sh[i] = 0;
    __syncthreads();

    // ============ phase 1: one-touch packed segment histograms =============
    // Chunk = 128 elements = 8 segments; int4 per lane (coalesced). Same-word
    // atomic collisions only among the 4 lanes of one segment over 18 words
    // (replay ~1.3). Byte counts <= 16: no carry.
    {
        int4 q[5];
        bool valid[5];
        if (bx >= 1 && bx <= 186) {
            // interior: unpadded base; element offset 1280*bx-512 % 4 == 0
            const int* __restrict__ basep = row + (gseg0 * SEGLEN - PAD);
            #pragma unroll
            for (int t = 0; t < 5; t++) {
                int c = wid + 4 * t;
                valid[t] = (c < CHUNKS);
                if (valid[t]) q[t] = *(const int4*)(basep + c * 128 + lane * 4);
            }
        } else {
            // edge CTAs (bx==0, bx==187): reflect-mapped scalar prefetch
            #pragma unroll
            for (int t = 0; t < 5; t++) {
                int c = wid + 4 * t;
                valid[t] = false;
                if (c < CHUNKS) {
                    int e   = c * 128 + lane * 4;
                    int seg = e >> 4;
                    if (seg < SEGS_PER_CTA && (gseg0 + seg) < TOTAL_SEGS) {
                        int j0 = gseg0 * SEGLEN + e;
                        q[t].x = row[reflect_idx(j0)];
                        q[t].y = row[reflect_idx(j0 + 1)];
                        q[t].z = row[reflect_idx(j0 + 2)];
                        q[t].w = row[reflect_idx(j0 + 3)];
                        valid[t] = true;
                    }
                }
            }
        }
        #pragma unroll
        for (int t = 0; t < 5; t++) {
            if (valid[t]) {
                int c   = wid + 4 * t;
                int seg = 8 * c + (lane >> 2);
                if (seg < SEGS_PER_CTA) {   // chunk 16 covers segs 128..135
                    atomicAdd(&sh[(uint32_t)(q[t].x >> 2) * PITCH + seg],
                              1u << ((q[t].x & 3) * 8));
                    atomicAdd(&sh[(uint32_t)(q[t].y >> 2) * PITCH + seg],
                              1u << ((q[t].y & 3) * 8));
                    atomicAdd(&sh[(uint32_t)(q[t].z >> 2) * PITCH + seg],
                              1u << ((q[t].z & 3) * 8));
                    atomicAdd(&sh[(uint32_t)(q[t].w >> 2) * PITCH + seg],
                              1u << ((q[t].w & 3) * 8));
                }
            }
        }
    }
    __syncthreads();

    // ============ phase 2: window sums + one slide (no atomics) ============
    // Warp handles windows w0 + 2*wid {+1}. Lane c<18 reads column c of the
    // byte-packed words (pitch 135: 135*c+s -> bank (7c+s)%32, distinct per c).
    // u8x4 -> two u16x2 accumulators; window sums <= 1024 fit u16; slide adds
    // before subtracting so fields never underflow... (u16 fields independent:
    // add/sub of in-range values keeps each field exact).
    const int wrel0 = 2 * wid;
    const int srel  = 10 * wrel0;
    const uint32_t* __restrict__ col = sh + lane * PITCH + srel;

    uint32_t accE = 0, accO = 0;
    if (lane < NWORDS) {
        #pragma unroll
        for (int k = 0; k < SEGS_PER_WIN; k++) {
            uint32_t u = col[k];
            accE += u & 0x00FF00FFu;          // bins (4c, 4c+2)
            accO += (u >> 8) & 0x00FF00FFu;   // bins (4c+1, 4c+3)
        }
    }
    scan_write(accE, accO, lane, orow, w0 + wrel0);

    if (lane < NWORDS) {
        #pragma unroll
        for (int k = 0; k < 10; k++) {
            uint32_t un = col[SEGS_PER_WIN + k];   // entering
            uint32_t uo = col[k];                  // leaving
            accE += (un & 0x00FF00FFu)        - (uo & 0x00FF00FFu);
            accO += ((un >> 8) & 0x00FF00FFu) - ((uo >> 8) & 0x00FF00FFu);
        }
    }
    scan_write(accE, accO, lane, orow, w0 + wrel0 + 1);
}

extern "C" void kernel_launch(void* const* d_in, const int* in_sizes, int n_in,
                              void* d_out, int out_size)
{
    const int* lbl = (const int*)d_in[0];   // [B, T] int32
    // d_in[1]: all-ones conv weight — irrelevant (window sum == histogram).
    float* out = (float*)d_out;             // [B, NOUT], compared as float32

    dim3 grid(CTAS_X, BATCH);
    label_majority_seg16s<<<grid, BLOCK>>>(lbl, out);
}